// round 1
// baseline (speedup 1.0000x reference)
#include <cuda_runtime.h>
#include <cuda_bf16.h>
#include <math_constants.h>

#define HW      4096
#define TOT     (HW*HW)              // 16,777,216
#define KSEL    8388607u             // (n-1)//2
#define NBIN    65536
#define NREP    32

// ---------------- device scratch (static, allocation-free) ----------------
__device__ unsigned int g_hist[NBIN * NREP];   // 8 MB replicated histogram
__device__ unsigned int g_counts[NBIN];
__device__ unsigned int g_k;
__device__ unsigned int g_selTop;
__device__ unsigned int g_selLow;
__device__ float        g_median;

// monotonic float-bits -> uint map (ascending float order == ascending uint order)
__device__ __forceinline__ unsigned int fmap(unsigned int b) {
    return (b & 0x80000000u) ? ~b : (b | 0x80000000u);
}

// ---------------- kernel 1: zero histogram (+ init k on first call) -------
__global__ void k_zero_hist(int initk) {
    unsigned int i = blockIdx.x * blockDim.x + threadIdx.x;   // 524288 threads
    if (i < (NBIN * NREP / 4)) {
        reinterpret_cast<uint4*>(g_hist)[i] = make_uint4(0u, 0u, 0u, 0u);
    }
    if (initk && i == 0) g_k = KSEL;
}

// ---------------- kernel 2: histogram pass (top16 or low16) ---------------
__global__ void k_hist(const float4* __restrict__ x4, int pass) {
    unsigned int rep = ((blockIdx.x << 3) + (threadIdx.x >> 5)) & (NREP - 1);
    unsigned int* hist = g_hist + rep * (unsigned)NBIN;
    unsigned int sel = g_selTop;
    unsigned int stride = gridDim.x * blockDim.x;
    for (unsigned int i = blockIdx.x * blockDim.x + threadIdx.x; i < (TOT / 4); i += stride) {
        float4 v = __ldg(&x4[i]);
        unsigned int m0 = fmap(__float_as_uint(v.x));
        unsigned int m1 = fmap(__float_as_uint(v.y));
        unsigned int m2 = fmap(__float_as_uint(v.z));
        unsigned int m3 = fmap(__float_as_uint(v.w));
        if (pass == 0) {
            atomicAdd(&hist[m0 >> 16], 1u);
            atomicAdd(&hist[m1 >> 16], 1u);
            atomicAdd(&hist[m2 >> 16], 1u);
            atomicAdd(&hist[m3 >> 16], 1u);
        } else {
            if ((m0 >> 16) == sel) atomicAdd(&hist[m0 & 0xFFFFu], 1u);
            if ((m1 >> 16) == sel) atomicAdd(&hist[m1 & 0xFFFFu], 1u);
            if ((m2 >> 16) == sel) atomicAdd(&hist[m2 & 0xFFFFu], 1u);
            if ((m3 >> 16) == sel) atomicAdd(&hist[m3 & 0xFFFFu], 1u);
        }
    }
}

// ---------------- kernel 3: reduce 32 replicas -> g_counts ----------------
__global__ void k_reduce() {
    unsigned int bin = blockIdx.x * blockDim.x + threadIdx.x;  // 65536 threads
    unsigned int s = 0;
#pragma unroll
    for (int r = 0; r < NREP; r++) s += g_hist[(unsigned)r * NBIN + bin];
    g_counts[bin] = s;
}

// ---------------- kernel 4: single-block scan; find bucket containing k ---
__global__ void k_scan_find(int pass) {
    __shared__ unsigned int part[1024];
    __shared__ unsigned int sh_k;
    int t = threadIdx.x;
    if (t == 0) sh_k = g_k;
    unsigned int s = 0;
    int base = t * 64;
    for (int i = 0; i < 64; i++) s += g_counts[base + i];
    part[t] = s;
    __syncthreads();
    for (int off = 1; off < 1024; off <<= 1) {
        unsigned int v = (t >= off) ? part[t - off] : 0u;
        __syncthreads();
        part[t] += v;
        __syncthreads();
    }
    unsigned int incl = part[t];
    unsigned int excl = incl - s;
    unsigned int k = sh_k;
    if (k >= excl && k < incl) {
        unsigned int run = excl;
        for (int i = 0; i < 64; i++) {
            unsigned int c = g_counts[base + i];
            if (k < run + c) {
                if (pass == 0) g_selTop = (unsigned)(base + i);
                else           g_selLow = (unsigned)(base + i);
                g_k = k - run;
                break;
            }
            run += c;
        }
    }
}

// ---------------- kernel 5: reconstruct median float ----------------------
__global__ void k_finalize_median() {
    unsigned int m = (g_selTop << 16) | g_selLow;
    unsigned int b = (m & 0x80000000u) ? (m ^ 0x80000000u) : ~m;
    g_median = __uint_as_float(b);
}

// ---------------- kernel 6: fused threshold + 7x7 maxpool + NMS -----------
// Tile: 128 (x) x 32 (y) outputs, halo 3 on each side.
#define TX 128
#define TY 32
#define HX (TX + 6)   // 134
#define HY (TY + 6)   // 38
#define XS_PITCH (HX + 2)   // 136 (pad for banks)
#define RM_PITCH (TX + 4)   // 132

__global__ __launch_bounds__(256) void k_nms(const float* __restrict__ x,
                                             float* __restrict__ out) {
    __shared__ float xs[HY][XS_PITCH];   // thresholded values (halo), OOB = -inf
    __shared__ float rm[HY][RM_PITCH];   // horizontal 7-max

    const float med = g_median;
    const int x0 = blockIdx.x * TX;
    const int y0 = blockIdx.y * TY;
    const int tid = threadIdx.x;
    const float NEG_INF = __int_as_float(0xff800000);

    // load halo tile, compute threshold on the fly
    for (int i = tid; i < HY * HX; i += 256) {
        int ly = i / HX, lx = i % HX;
        int gy = y0 - 3 + ly, gx = x0 - 3 + lx;
        float thr;
        if ((unsigned)gy < HW && (unsigned)gx < HW) {
            float v = __ldg(&x[gy * HW + gx]);
            thr = (v < med) ? 0.0f : v;
        } else {
            thr = NEG_INF;
        }
        xs[ly][lx] = thr;
    }
    __syncthreads();

    // horizontal 7-max: rm[ly][lx] = max(xs[ly][lx .. lx+6])
    for (int i = tid; i < HY * TX; i += 256) {
        int ly = i / TX, lx = i % TX;
        float m = xs[ly][lx];
#pragma unroll
        for (int d = 1; d < 7; d++) m = fmaxf(m, xs[ly][lx + d]);
        rm[ly][lx] = m;
    }
    __syncthreads();

    // vertical 7-max + binarize + multiply; 16 rows per thread, coalesced in x
    const int xo = tid & (TX - 1);
    const int yb = (tid >> 7) * 16;
#pragma unroll
    for (int r = 0; r < 16; r++) {
        int yo = yb + r;
        float p = rm[yo][xo];
#pragma unroll
        for (int d = 1; d < 7; d++) p = fmaxf(p, rm[yo + d][xo]);
        float thr = xs[yo + 3][xo + 3];
        int gidx = (y0 + yo) * HW + (x0 + xo);
        float xv = __ldg(&x[gidx]);
        out[gidx] = (thr == p) ? xv : 0.0f;
    }
}

// ---------------- launch sequence -----------------------------------------
extern "C" void kernel_launch(void* const* d_in, const int* in_sizes, int n_in,
                              void* d_out, int out_size) {
    const float*  x  = (const float*)d_in[0];
    const float4* x4 = (const float4*)d_in[0];
    float* out = (float*)d_out;
    (void)in_sizes; (void)n_in; (void)out_size;

    // pass 1: top 16 bits
    k_zero_hist<<<2048, 256>>>(1);
    k_hist<<<2048, 256>>>(x4, 0);
    k_reduce<<<256, 256>>>();
    k_scan_find<<<1, 1024>>>(0);
    // pass 2: low 16 bits within selected top bucket
    k_zero_hist<<<2048, 256>>>(0);
    k_hist<<<2048, 256>>>(x4, 1);
    k_reduce<<<256, 256>>>();
    k_scan_find<<<1, 1024>>>(1);
    k_finalize_median<<<1, 1>>>();
    // fused NMS
    dim3 grid(HW / TX, HW / TY);
    k_nms<<<grid, 256>>>(x, out);
}